// round 2
// baseline (speedup 1.0000x reference)
#include <cuda_runtime.h>
#include <math.h>

// Problem constants (fixed by the dataset)
#define NN 2048
#define MM 2048
#define KC 8
#define DD 64

// Compact potential layout: [fab(N) | gab(M) | faa(N) | gbb(M)]
#define FAB_OFF 0
#define GAB_OFF NN
#define FAA_OFF (NN + MM)
#define GBB_OFF (2 * NN + MM)
#define POT_SZ  (2 * (NN + MM))

#define LOG2E_F 1.4426950408889634f
#define LN2_F   0.6931471805599453f

// -------------------- static device scratch (no allocation allowed) ---------
__device__ int   g_predx[NN];
__device__ int   g_ix[NN], g_iy[MM];        // member indices grouped by cluster
__device__ int   g_clx[NN], g_cly[MM];      // cluster of compact position
__device__ int   g_cntx[KC], g_cnty[KC];
__device__ int   g_offx[KC + 1], g_offy[KC + 1];
__device__ int   g_offXY[KC + 1], g_offYX[KC + 1], g_offXX[KC + 1], g_offYY[KC + 1];
__device__ float g_l2cx[KC], g_l2cy[KC];    // log2(max(cnt,1))
__device__ int   g_valid[KC];
__device__ float g_lossfil;
__device__ int   g_rtOff[4 * KC + 1];       // row-tile prefix for cost build
__device__ int   g_nRT;
__device__ float g_hx[NN], g_hy[MM];        // 0.5*||p||^2
// Compact cost matrices (worst case = one cluster owns everything)
__device__ float g_Cxy[(size_t)NN * MM];
__device__ float g_Cyx[(size_t)NN * MM];
__device__ float g_Cxx[(size_t)NN * NN];
__device__ float g_Cyy[(size_t)MM * MM];
__device__ float g_pot[2][POT_SZ];          // ping-pong potentials

// -------------------- 1) kmeans assignment ---------------------------------
__global__ void k_assign(const float* __restrict__ x, const float* __restrict__ cc) {
    __shared__ float scc[KC * DD];
    for (int idx = threadIdx.x; idx < KC * DD; idx += blockDim.x) scc[idx] = cc[idx];
    __syncthreads();
    int i = blockIdx.x * blockDim.x + threadIdx.x;
    if (i >= NN) return;
    float xr[DD];
    const float4* xv = reinterpret_cast<const float4*>(x + (size_t)i * DD);
#pragma unroll
    for (int q = 0; q < DD / 4; q++) {
        float4 v = xv[q];
        xr[q * 4 + 0] = v.x; xr[q * 4 + 1] = v.y; xr[q * 4 + 2] = v.z; xr[q * 4 + 3] = v.w;
    }
    float best = 3.4e38f; int bk = 0;
#pragma unroll
    for (int k = 0; k < KC; k++) {
        float s = 0.f;
#pragma unroll 16
        for (int d = 0; d < DD; d++) {
            float t = xr[d] - scc[k * DD + d];
            s = fmaf(t, t, s);
        }
        if (s < best) { best = s; bk = k; }  // strict < keeps first argmin like jnp
    }
    g_predx[i] = bk;
}

// -------------------- 2) half squared norms --------------------------------
__global__ void k_norms(const float* __restrict__ x, const float* __restrict__ y) {
    int t = blockIdx.x * blockDim.x + threadIdx.x;
    if (t < NN) {
        const float4* v = reinterpret_cast<const float4*>(x + (size_t)t * DD);
        float s = 0.f;
#pragma unroll
        for (int q = 0; q < DD / 4; q++) { float4 a = v[q]; s += a.x*a.x + a.y*a.y + a.z*a.z + a.w*a.w; }
        g_hx[t] = 0.5f * s;
    } else if (t < NN + MM) {
        int j = t - NN;
        const float4* v = reinterpret_cast<const float4*>(y + (size_t)j * DD);
        float s = 0.f;
#pragma unroll
        for (int q = 0; q < DD / 4; q++) { float4 a = v[q]; s += a.x*a.x + a.y*a.y + a.z*a.z + a.w*a.w; }
        g_hy[j] = 0.5f * s;
    }
}

// -------------------- 3) deterministic member lists + offsets --------------
// predy viewed as int32 words. If the real dtype is int64 (little-endian,
// values 0..7) every odd word is 0 -> stride 2. If int32, odd words are 1024
// random values in 0..7 (P(all zero) = 8^-1024) -> stride 1.
__global__ void k_lists(const int* __restrict__ predy32, const float* __restrict__ fill) {
    __shared__ int sBase[2][KC];
    __shared__ int sCnt[2][KC];
    __shared__ int sOr;
    int w = threadIdx.x >> 5, lane = threadIdx.x & 31;

    if (threadIdx.x == 0) sOr = 0;
    __syncthreads();
    int orv = 0;
    for (int i = threadIdx.x; i < MM / 2; i += blockDim.x) orv |= predy32[2 * i + 1];
    atomicOr(&sOr, orv);
    __syncthreads();
    const int stride = (sOr == 0) ? 2 : 1;

    if (w < 2) {
        int nElem = (w == 0) ? NN : MM;
        // pass 1: histogram
        int cnt[KC];
#pragma unroll
        for (int k = 0; k < KC; k++) cnt[k] = 0;
        for (int ch = 0; ch < nElem / 32; ch++) {
            int i = ch * 32 + lane;
            int v = (w == 0) ? g_predx[i] : (predy32[i * stride] & 7);
#pragma unroll
            for (int k = 0; k < KC; k++) cnt[k] += (v == k);
        }
#pragma unroll
        for (int k = 0; k < KC; k++) {
            int s = cnt[k];
            for (int o = 16; o; o >>= 1) s += __shfl_down_sync(0xffffffffu, s, o);
            if (lane == 0) sCnt[w][k] = s;
        }
        __syncwarp();
        if (lane == 0) {
            int off = 0;
            for (int k = 0; k < KC; k++) {
                int c = sCnt[w][k];
                sBase[w][k] = off;
                if (w == 0) { g_cntx[k] = c; g_offx[k] = off; }
                else        { g_cnty[k] = c; g_offy[k] = off; }
                off += c;
            }
            if (w == 0) g_offx[KC] = off; else g_offy[KC] = off;
        }
        __syncwarp();
        // pass 2: stable scatter (order of original index preserved)
        for (int ch = 0; ch < nElem / 32; ch++) {
            int i = ch * 32 + lane;
            int v = (w == 0) ? g_predx[i] : (predy32[i * stride] & 7);
            unsigned mask = __match_any_sync(0xffffffffu, v);
            unsigned lt = (1u << lane) - 1u;
            int rank = __popc(mask & lt);
            int myBase = sBase[w][v];
            __syncwarp();
            int pos = myBase + rank;
            if (w == 0) { g_ix[pos] = i; g_clx[pos] = v; }
            else        { g_iy[pos] = i; g_cly[pos] = v; }
            if ((mask & lt) == 0) sBase[w][v] = myBase + __popc(mask); // leader
            __syncwarp();
        }
    }
    __syncthreads();
    if (threadIdx.x == 0) {
        float lf = 0.f;
        int oXY = 0, oYX = 0, oXX = 0, oYY = 0;
        for (int k = 0; k < KC; k++) {
            int cx = g_cntx[k], cy = g_cnty[k];
            float d = (float)cx / (float)NN - fill[k];
            lf += d * d;
            g_offXY[k] = oXY; g_offYX[k] = oYX; g_offXX[k] = oXX; g_offYY[k] = oYY;
            oXY += cx * cy; oYX += cy * cx; oXX += cx * cx; oYY += cy * cy;
            g_l2cx[k] = log2f((float)(cx > 0 ? cx : 1));
            g_l2cy[k] = log2f((float)(cy > 0 ? cy : 1));
            g_valid[k] = (cx > 0 && cy > 0) ? 1 : 0;
        }
        g_offXY[KC] = oXY; g_offYX[KC] = oYX; g_offXX[KC] = oXX; g_offYY[KC] = oYY;
        g_lossfil = lf / (float)KC;
        // row-tile prefix for cost build: families 0..3 rows = cx,cy,cx,cy
        g_rtOff[0] = 0;
        for (int f = 0; f < 4; f++)
            for (int k = 0; k < KC; k++) {
                int rows = (f == 0 || f == 2) ? g_cntx[k] : g_cnty[k];
                int idx = f * KC + k;
                g_rtOff[idx + 1] = g_rtOff[idx] + (rows + 31) / 32;
            }
        g_nRT = g_rtOff[4 * KC];
    }
    __syncthreads();
    for (int i = threadIdx.x; i < POT_SZ; i += blockDim.x) g_pot[0][i] = 0.f; // init potentials
}

// -------------------- 4) compact cost submatrices --------------------------
// One block per 32-row tile; loops over 32-col tiles. C = max(hr + hc - dot, 0)
__global__ void k_cost(const float* __restrict__ x, const float* __restrict__ y) {
    __shared__ float sR[32][DD + 1];
    __shared__ float sC[32][DD + 1];
    __shared__ float sHr[32], sHc[32];
    __shared__ int sOff[4 * KC + 1];
    if (threadIdx.x < 4 * KC + 1) sOff[threadIdx.x] = g_rtOff[threadIdx.x];
    __syncthreads();
    int rt = blockIdx.x;
    if (rt >= g_nRT) return;
    int e = 0;
    while (rt >= sOff[e + 1]) e++;
    int f = e >> 3, k = e & 7;
    int tr = rt - sOff[e];
    int cx = g_cntx[k], cy = g_cnty[k], ox = g_offx[k], oy = g_offy[k];
    int nr, nc, obase;
    const int *rl, *cl; const float *rp, *cp, *rh, *chv; float* outp;
    if (f == 0)      { nr = cx; nc = cy; rl = g_ix + ox; cl = g_iy + oy; rp = x; cp = y; rh = g_hx; chv = g_hy; outp = g_Cxy; obase = g_offXY[k]; }
    else if (f == 1) { nr = cy; nc = cx; rl = g_iy + oy; cl = g_ix + ox; rp = y; cp = x; rh = g_hy; chv = g_hx; outp = g_Cyx; obase = g_offYX[k]; }
    else if (f == 2) { nr = cx; nc = cx; rl = g_ix + ox; cl = g_ix + ox; rp = x; cp = x; rh = g_hx; chv = g_hx; outp = g_Cxx; obase = g_offXX[k]; }
    else             { nr = cy; nc = cy; rl = g_iy + oy; cl = g_iy + oy; rp = y; cp = y; rh = g_hy; chv = g_hy; outp = g_Cyy; obase = g_offYY[k]; }
    if (nr == 0 || nc == 0) return;
    int r0 = tr * 32;
    for (int idx = threadIdx.x; idx < 32 * DD; idx += 256) {
        int r = idx >> 6, d = idx & 63;
        int rr = r0 + r;
        int gi = (rr < nr) ? rl[rr] : rl[0];
        sR[r][d] = rp[(size_t)gi * DD + d];
    }
    if (threadIdx.x < 32) {
        int rr = r0 + threadIdx.x;
        sHr[threadIdx.x] = (rr < nr) ? rh[rl[rr]] : 0.f;
    }
    __syncthreads();
    int r = threadIdx.x >> 3, cb = (threadIdx.x & 7) * 4;
    for (int c0 = 0; c0 < nc; c0 += 32) {
        for (int idx = threadIdx.x; idx < 32 * DD; idx += 256) {
            int c = idx >> 6, d = idx & 63;
            int cc = c0 + c;
            int gi = (cc < nc) ? cl[cc] : cl[0];
            sC[c][d] = cp[(size_t)gi * DD + d];
        }
        if (threadIdx.x < 32) {
            int cc = c0 + threadIdx.x;
            sHc[threadIdx.x] = (cc < nc) ? chv[cl[cc]] : 0.f;
        }
        __syncthreads();
        float a0 = 0.f, a1 = 0.f, a2 = 0.f, a3 = 0.f;
#pragma unroll 16
        for (int d = 0; d < DD; d++) {
            float rv = sR[r][d];
            a0 = fmaf(rv, sC[cb + 0][d], a0);
            a1 = fmaf(rv, sC[cb + 1][d], a1);
            a2 = fmaf(rv, sC[cb + 2][d], a2);
            a3 = fmaf(rv, sC[cb + 3][d], a3);
        }
        int rr = r0 + r;
        if (rr < nr) {
            float hr = sHr[r];
            size_t rowb = (size_t)obase + (size_t)rr * nc + c0 + cb;
            if (c0 + cb + 0 < nc) outp[rowb + 0] = fmaxf(hr + sHc[cb + 0] - a0, 0.f);
            if (c0 + cb + 1 < nc) outp[rowb + 1] = fmaxf(hr + sHc[cb + 1] - a1, 0.f);
            if (c0 + cb + 2 < nc) outp[rowb + 2] = fmaxf(hr + sHc[cb + 2] - a2, 0.f);
            if (c0 + cb + 3 < nc) outp[rowb + 3] = fmaxf(hr + sHc[cb + 3] - a3, 0.f);
        }
        __syncthreads();
    }
}

// -------------------- 5) one Sinkhorn round: 4 softmin families ------------
// warp per output row; two-pass stabilized logsumexp in log2 domain.
__global__ void k_softmin(int bin, int bout, float eps, float inv_eps, int finalMode) {
    const float* __restrict__ potIn = g_pot[bin];
    float* __restrict__ potOut = g_pot[bout];
    int w = threadIdx.x >> 5, lane = threadIdx.x & 31;
    int row = blockIdx.x * 8 + w;
    int fam = row >> 11;         // 2048 rows per family
    int p = row & 2047;
    int k, n, outIdx;
    const float *Crow, *pot;
    float b2;
    if (fam == 0) {              // ft: rows x, reduce over y with gab
        k = g_clx[p]; n = g_cnty[k];
        int i = p - g_offx[k];
        Crow = g_Cxy + (size_t)g_offXY[k] + (size_t)i * n;
        pot = potIn + GAB_OFF + g_offy[k];
        b2 = -g_l2cy[k]; outIdx = FAB_OFF + p;
    } else if (fam == 1) {       // gt: rows y, reduce over x with fab
        k = g_cly[p]; n = g_cntx[k];
        int j = p - g_offy[k];
        Crow = g_Cyx + (size_t)g_offYX[k] + (size_t)j * n;
        pot = potIn + FAB_OFF + g_offx[k];
        b2 = -g_l2cx[k]; outIdx = GAB_OFF + p;
    } else if (fam == 2) {       // faa
        k = g_clx[p]; n = g_cntx[k];
        int i = p - g_offx[k];
        Crow = g_Cxx + (size_t)g_offXX[k] + (size_t)i * n;
        pot = potIn + FAA_OFF + g_offx[k];
        b2 = -g_l2cx[k]; outIdx = FAA_OFF + p;
    } else {                     // gbb
        k = g_cly[p]; n = g_cnty[k];
        int j = p - g_offy[k];
        Crow = g_Cyy + (size_t)g_offYY[k] + (size_t)j * n;
        pot = potIn + GBB_OFF + g_offy[k];
        b2 = -g_l2cy[k]; outIdx = GBB_OFF + p;
    }
    if (n == 0) { if (lane == 0) potOut[outIdx] = 0.f; return; }
    float s1 = inv_eps * LOG2E_F;
    // pass 1: max (cheap: fma + fmax on alu pipes, no MUFU)
    float m2 = -3.4e38f;
    for (int c = lane; c < n; c += 32) {
        float t2 = (pot[c] - Crow[c]) * s1 + b2;
        m2 = fmaxf(m2, t2);
    }
#pragma unroll
    for (int o = 16; o; o >>= 1) m2 = fmaxf(m2, __shfl_xor_sync(0xffffffffu, m2, o));
    // pass 2: exp2 + sum (L1-hot reload)
    float S = 0.f;
    for (int c = lane; c < n; c += 32) {
        float t2 = (pot[c] - Crow[c]) * s1 + b2;
        S += exp2f(t2 - m2);
    }
#pragma unroll
    for (int o = 16; o; o >>= 1) S += __shfl_xor_sync(0xffffffffu, S, o);
    if (lane == 0) {
        float lse = (m2 + log2f(S)) * LN2_F;
        float outv = -eps * lse;
        potOut[outIdx] = finalMode ? outv : 0.5f * (potIn[outIdx] + outv);
    }
}

// -------------------- 6) final divergence reduction ------------------------
__global__ void k_reduce(int buf, float* __restrict__ out) {
    __shared__ float sred[256];
    const float* pf = g_pot[buf];
    float acc = 0.f;
    for (int p = threadIdx.x; p < NN; p += 256) {
        int k = g_clx[p];
        if (g_valid[k]) acc += (pf[FAB_OFF + p] - pf[FAA_OFF + p]) / (float)g_cntx[k];
    }
    for (int p = threadIdx.x; p < MM; p += 256) {
        int k = g_cly[p];
        if (g_valid[k]) acc += (pf[GAB_OFF + p] - pf[GBB_OFF + p]) / (float)g_cnty[k];
    }
    sred[threadIdx.x] = acc;
    __syncthreads();
    for (int s = 128; s; s >>= 1) {
        if (threadIdx.x < s) sred[threadIdx.x] += sred[threadIdx.x + s];
        __syncthreads();
    }
    if (threadIdx.x == 0) out[0] = sred[0] + g_lossfil;
}

// -------------------- host launch ------------------------------------------
extern "C" void kernel_launch(void* const* d_in, const int* in_sizes, int n_in,
                              void* d_out, int out_size) {
    const float* x    = (const float*)d_in[0];
    const float* cc   = (const float*)d_in[1];
    const float* fill = (const float*)d_in[2];
    const float* y    = (const float*)d_in[3];
    const int*   pred = (const int*)d_in[4];   // int32 or int64 (auto-detected on device)
    float* out = (float*)d_out;

    k_assign<<<(NN + 127) / 128, 128>>>(x, cc);
    k_norms<<<(NN + MM + 255) / 256, 256>>>(x, y);
    k_lists<<<1, 64>>>(pred, fill);
    k_cost<<<4 * (KC + NN / 32), 256>>>(x, y);   // 288 blocks covers worst-case tiles

    // eps schedule: e = 16 * 0.64^t while e > 0.0025, then append 0.0025 (21 entries)
    float epsv[40]; int ns = 0;
    double e = 16.0; const double emin = 0.0025;
    while (e > emin) { epsv[ns++] = (float)e; e *= 0.64; }
    epsv[ns++] = (float)emin;

    for (int s = 0; s < ns; s++)
        k_softmin<<<1024, 256>>>(s & 1, (s + 1) & 1, epsv[s], (float)(1.0 / (double)epsv[s]), 0);
    // final extrapolation at eps_min (no averaging)
    k_softmin<<<1024, 256>>>(ns & 1, (ns + 1) & 1, epsv[ns - 1], (float)(1.0 / (double)epsv[ns - 1]), 1);
    k_reduce<<<1, 256>>>((ns + 1) & 1, out);
}

// round 3
// speedup vs baseline: 1.1105x; 1.1105x over previous
#include <cuda_runtime.h>
#include <math.h>

// Problem constants (fixed by the dataset)
#define NN 2048
#define MM 2048
#define KC 8
#define DD 64

// Compact potential layout: [fab(N) | gab(M) | faa(N) | gbb(M)]
#define FAB_OFF 0
#define GAB_OFF NN
#define FAA_OFF (NN + MM)
#define GBB_OFF (2 * NN + MM)
#define POT_SZ  (2 * (NN + MM))

#define LOG2E_F 1.4426950408889634f
#define LN2_F   0.6931471805599453f

#define GRIDB 148          // persistent kernel: one block per SM (wave-1 placement is 1:1)

// -------------------- static device scratch (no allocation allowed) ---------
__device__ int   g_predx[NN];
__device__ int   g_ix[NN], g_iy[MM];        // member indices grouped by cluster
__device__ int   g_clx[NN], g_cly[MM];      // cluster of compact position
__device__ int   g_cntx[KC], g_cnty[KC];
__device__ int   g_offx[KC + 1], g_offy[KC + 1];
__device__ int   g_offXY[KC + 1], g_offYX[KC + 1], g_offXX[KC + 1], g_offYY[KC + 1];
__device__ float g_l2cx[KC], g_l2cy[KC];    // log2(max(cnt,1))
__device__ int   g_valid[KC];
__device__ float g_lossfil;
__device__ int   g_rtOff[4 * KC + 1];       // 64-row tile prefix for cost build
__device__ int   g_nRT;
__device__ float g_hx[NN], g_hy[MM];        // 0.5*||p||^2
__device__ unsigned g_barCnt;               // grid barrier counter (reset at kernel end)
// Compact cost matrices (worst case = one cluster owns everything)
__device__ float g_Cxy[(size_t)NN * MM];
__device__ float g_Cyx[(size_t)NN * MM];
__device__ float g_Cxx[(size_t)NN * NN];
__device__ float g_Cyy[(size_t)MM * MM];
__device__ float g_pot[2][POT_SZ];          // ping-pong potentials

__device__ __forceinline__ float ex2_fast(float x) {
    float r;
    asm("ex2.approx.ftz.f32 %0, %1;" : "=f"(r) : "f"(x));
    return r;
}

// -------------------- 1) kmeans assignment ---------------------------------
__global__ void k_assign(const float* __restrict__ x, const float* __restrict__ cc) {
    __shared__ float scc[KC * DD];
    for (int idx = threadIdx.x; idx < KC * DD; idx += blockDim.x) scc[idx] = cc[idx];
    __syncthreads();
    int i = blockIdx.x * blockDim.x + threadIdx.x;
    if (i >= NN) return;
    float xr[DD];
    const float4* xv = reinterpret_cast<const float4*>(x + (size_t)i * DD);
#pragma unroll
    for (int q = 0; q < DD / 4; q++) {
        float4 v = xv[q];
        xr[q * 4 + 0] = v.x; xr[q * 4 + 1] = v.y; xr[q * 4 + 2] = v.z; xr[q * 4 + 3] = v.w;
    }
    float best = 3.4e38f; int bk = 0;
#pragma unroll
    for (int k = 0; k < KC; k++) {
        float s = 0.f;
#pragma unroll 16
        for (int d = 0; d < DD; d++) {
            float t = xr[d] - scc[k * DD + d];
            s = fmaf(t, t, s);
        }
        if (s < best) { best = s; bk = k; }  // strict < keeps first argmin like jnp
    }
    g_predx[i] = bk;
}

// -------------------- 2) half squared norms --------------------------------
__global__ void k_norms(const float* __restrict__ x, const float* __restrict__ y) {
    int t = blockIdx.x * blockDim.x + threadIdx.x;
    if (t < NN) {
        const float4* v = reinterpret_cast<const float4*>(x + (size_t)t * DD);
        float s = 0.f;
#pragma unroll
        for (int q = 0; q < DD / 4; q++) { float4 a = v[q]; s += a.x*a.x + a.y*a.y + a.z*a.z + a.w*a.w; }
        g_hx[t] = 0.5f * s;
    } else if (t < NN + MM) {
        int j = t - NN;
        const float4* v = reinterpret_cast<const float4*>(y + (size_t)j * DD);
        float s = 0.f;
#pragma unroll
        for (int q = 0; q < DD / 4; q++) { float4 a = v[q]; s += a.x*a.x + a.y*a.y + a.z*a.z + a.w*a.w; }
        g_hy[j] = 0.5f * s;
    }
}

// -------------------- 3) deterministic member lists + offsets --------------
// predy viewed as int32 words. If the real dtype is int64 (little-endian,
// values 0..7) every odd word is 0 -> stride 2. If int32, odd words are 1024
// random values in 0..7 (P(all zero) = 8^-1024) -> stride 1.
__global__ void k_lists(const int* __restrict__ predy32, const float* __restrict__ fill) {
    __shared__ int sBase[2][KC];
    __shared__ int sCnt[2][KC];
    __shared__ int sOr;
    int w = threadIdx.x >> 5, lane = threadIdx.x & 31;

    if (threadIdx.x == 0) sOr = 0;
    __syncthreads();
    int orv = 0;
    for (int i = threadIdx.x; i < MM / 2; i += blockDim.x) orv |= predy32[2 * i + 1];
    atomicOr(&sOr, orv);
    __syncthreads();
    const int stride = (sOr == 0) ? 2 : 1;

    if (w < 2) {
        int nElem = (w == 0) ? NN : MM;
        // pass 1: histogram
        int cnt[KC];
#pragma unroll
        for (int k = 0; k < KC; k++) cnt[k] = 0;
        for (int ch = 0; ch < nElem / 32; ch++) {
            int i = ch * 32 + lane;
            int v = (w == 0) ? g_predx[i] : (predy32[i * stride] & 7);
#pragma unroll
            for (int k = 0; k < KC; k++) cnt[k] += (v == k);
        }
#pragma unroll
        for (int k = 0; k < KC; k++) {
            int s = cnt[k];
            for (int o = 16; o; o >>= 1) s += __shfl_down_sync(0xffffffffu, s, o);
            if (lane == 0) sCnt[w][k] = s;
        }
        __syncwarp();
        if (lane == 0) {
            int off = 0;
            for (int k = 0; k < KC; k++) {
                int c = sCnt[w][k];
                sBase[w][k] = off;
                if (w == 0) { g_cntx[k] = c; g_offx[k] = off; }
                else        { g_cnty[k] = c; g_offy[k] = off; }
                off += c;
            }
            if (w == 0) g_offx[KC] = off; else g_offy[KC] = off;
        }
        __syncwarp();
        // pass 2: stable scatter (order of original index preserved)
        for (int ch = 0; ch < nElem / 32; ch++) {
            int i = ch * 32 + lane;
            int v = (w == 0) ? g_predx[i] : (predy32[i * stride] & 7);
            unsigned mask = __match_any_sync(0xffffffffu, v);
            unsigned lt = (1u << lane) - 1u;
            int rank = __popc(mask & lt);
            int myBase = sBase[w][v];
            __syncwarp();
            int pos = myBase + rank;
            if (w == 0) { g_ix[pos] = i; g_clx[pos] = v; }
            else        { g_iy[pos] = i; g_cly[pos] = v; }
            if ((mask & lt) == 0) sBase[w][v] = myBase + __popc(mask); // leader
            __syncwarp();
        }
    }
    __syncthreads();
    if (threadIdx.x == 0) {
        float lf = 0.f;
        int oXY = 0, oYX = 0, oXX = 0, oYY = 0;
        for (int k = 0; k < KC; k++) {
            int cx = g_cntx[k], cy = g_cnty[k];
            float d = (float)cx / (float)NN - fill[k];
            lf += d * d;
            g_offXY[k] = oXY; g_offYX[k] = oYX; g_offXX[k] = oXX; g_offYY[k] = oYY;
            oXY += cx * cy; oYX += cy * cx; oXX += cx * cx; oYY += cy * cy;
            g_l2cx[k] = log2f((float)(cx > 0 ? cx : 1));
            g_l2cy[k] = log2f((float)(cy > 0 ? cy : 1));
            g_valid[k] = (cx > 0 && cy > 0) ? 1 : 0;
        }
        g_offXY[KC] = oXY; g_offYX[KC] = oYX; g_offXX[KC] = oXX; g_offYY[KC] = oYY;
        g_lossfil = lf / (float)KC;
        // row-tile prefix for cost build (64-row tiles): families 0..3 rows = cx,cy,cx,cy
        g_rtOff[0] = 0;
        for (int f = 0; f < 4; f++)
            for (int k = 0; k < KC; k++) {
                int rows = (f == 0 || f == 2) ? g_cntx[k] : g_cnty[k];
                int idx = f * KC + k;
                g_rtOff[idx + 1] = g_rtOff[idx] + (rows + 63) / 64;
            }
        g_nRT = g_rtOff[4 * KC];
    }
    __syncthreads();
    for (int i = threadIdx.x; i < POT_SZ; i += blockDim.x) g_pot[0][i] = 0.f; // init potentials
}

// -------------------- 4) compact cost submatrices --------------------------
// One block per 64-row tile; loops over 64-col chunks. 1024 threads, 2x2
// micro-tile per thread. C = max(hr + hc - dot, 0)
__global__ __launch_bounds__(1024, 1) void k_cost(const float* __restrict__ x,
                                                  const float* __restrict__ y) {
    __shared__ float sR[64][65];
    __shared__ float sC[64][65];
    __shared__ float sHr[64], sHc[64];
    __shared__ int sOff[4 * KC + 1];
    int tid = threadIdx.x;
    if (tid < 4 * KC + 1) sOff[tid] = g_rtOff[tid];
    __syncthreads();
    int rt = blockIdx.x;
    if (rt >= g_nRT) return;
    int e = 0;
    while (rt >= sOff[e + 1]) e++;
    int f = e >> 3, k = e & 7;
    int tr = rt - sOff[e];
    int cx = g_cntx[k], cy = g_cnty[k], ox = g_offx[k], oy = g_offy[k];
    int nr, nc, obase;
    const int *rl, *cl; const float *rp, *cp, *rh, *chv; float* outp;
    if (f == 0)      { nr = cx; nc = cy; rl = g_ix + ox; cl = g_iy + oy; rp = x; cp = y; rh = g_hx; chv = g_hy; outp = g_Cxy; obase = g_offXY[k]; }
    else if (f == 1) { nr = cy; nc = cx; rl = g_iy + oy; cl = g_ix + ox; rp = y; cp = x; rh = g_hy; chv = g_hx; outp = g_Cyx; obase = g_offYX[k]; }
    else if (f == 2) { nr = cx; nc = cx; rl = g_ix + ox; cl = g_ix + ox; rp = x; cp = x; rh = g_hx; chv = g_hx; outp = g_Cxx; obase = g_offXX[k]; }
    else             { nr = cy; nc = cy; rl = g_iy + oy; cl = g_iy + oy; rp = y; cp = y; rh = g_hy; chv = g_hy; outp = g_Cyy; obase = g_offYY[k]; }
    if (nr == 0 || nc == 0) return;
    int r0 = tr * 64;
    // fill row tile: 64 rows x 64 dims (coalesced 256B per row)
    for (int idx = tid; idx < 64 * DD; idx += 1024) {
        int r = idx >> 6, d = idx & 63;
        int rr = r0 + r;
        int gi = (rr < nr) ? rl[rr] : rl[0];
        sR[r][d] = rp[(size_t)gi * DD + d];
    }
    if (tid < 64) {
        int rr = r0 + tid;
        sHr[tid] = (rr < nr) ? rh[rl[rr]] : 0.f;
    }
    __syncthreads();
    int w = tid >> 5, l = tid & 31;
    int rA = 2 * w, rB = 2 * w + 1;
    for (int c0 = 0; c0 < nc; c0 += 64) {
        for (int idx = tid; idx < 64 * DD; idx += 1024) {
            int c = idx >> 6, d = idx & 63;
            int cc = c0 + c;
            int gi = (cc < nc) ? cl[cc] : cl[0];
            sC[c][d] = cp[(size_t)gi * DD + d];
        }
        if (tid < 64) {
            int cc = c0 + tid;
            sHc[tid] = (cc < nc) ? chv[cl[cc]] : 0.f;
        }
        __syncthreads();
        float a00 = 0.f, a01 = 0.f, a10 = 0.f, a11 = 0.f;
#pragma unroll 16
        for (int d = 0; d < DD; d++) {
            float rv0 = sR[rA][d];      // broadcast within warp
            float rv1 = sR[rB][d];      // broadcast within warp
            float cv0 = sC[l][d];       // conflict-free (65-float stride)
            float cv1 = sC[l + 32][d];
            a00 = fmaf(rv0, cv0, a00);
            a01 = fmaf(rv0, cv1, a01);
            a10 = fmaf(rv1, cv0, a10);
            a11 = fmaf(rv1, cv1, a11);
        }
        int rrA = r0 + rA, rrB = r0 + rB;
        int cA = c0 + l, cB = c0 + l + 32;
        if (rrA < nr) {
            float hr = sHr[rA];
            size_t rowb = (size_t)obase + (size_t)rrA * nc;
            if (cA < nc) outp[rowb + cA] = fmaxf(hr + sHc[l] - a00, 0.f);
            if (cB < nc) outp[rowb + cB] = fmaxf(hr + sHc[l + 32] - a01, 0.f);
        }
        if (rrB < nr) {
            float hr = sHr[rB];
            size_t rowb = (size_t)obase + (size_t)rrB * nc;
            if (cA < nc) outp[rowb + cA] = fmaxf(hr + sHc[l] - a10, 0.f);
            if (cB < nc) outp[rowb + cB] = fmaxf(hr + sHc[l + 32] - a11, 0.f);
        }
        __syncthreads();
    }
}

// -------------------- 5) persistent fused Sinkhorn rounds ------------------
__device__ __forceinline__ void grid_bar(unsigned target) {
    __syncthreads();
    if (threadIdx.x == 0) {
        __threadfence();
        atomicAdd(&g_barCnt, 1u);
        while (*((volatile unsigned*)&g_barCnt) < target) { }
        __threadfence();
    }
    __syncthreads();
}

__device__ __forceinline__ void sink_row(int row, const float* __restrict__ potIn,
                                         float* __restrict__ potOut,
                                         float eps, float s1, int finalMode, int lane) {
    int fam = row >> 11;         // 2048 rows per family
    int p = row & 2047;
    int k, n, outIdx;
    const float *Crow, *pot;
    float b2;
    if (fam == 0) {              // ft: rows x, reduce over y with gab
        k = g_clx[p]; n = g_cnty[k];
        int i = p - g_offx[k];
        Crow = g_Cxy + (size_t)g_offXY[k] + (size_t)i * n;
        pot = potIn + GAB_OFF + g_offy[k];
        b2 = -g_l2cy[k]; outIdx = FAB_OFF + p;
    } else if (fam == 1) {       // gt: rows y, reduce over x with fab
        k = g_cly[p]; n = g_cntx[k];
        int j = p - g_offy[k];
        Crow = g_Cyx + (size_t)g_offYX[k] + (size_t)j * n;
        pot = potIn + FAB_OFF + g_offx[k];
        b2 = -g_l2cx[k]; outIdx = GAB_OFF + p;
    } else if (fam == 2) {       // faa
        k = g_clx[p]; n = g_cntx[k];
        int i = p - g_offx[k];
        Crow = g_Cxx + (size_t)g_offXX[k] + (size_t)i * n;
        pot = potIn + FAA_OFF + g_offx[k];
        b2 = -g_l2cx[k]; outIdx = FAA_OFF + p;
    } else {                     // gbb
        k = g_cly[p]; n = g_cnty[k];
        int j = p - g_offy[k];
        Crow = g_Cyy + (size_t)g_offYY[k] + (size_t)j * n;
        pot = potIn + GBB_OFF + g_offy[k];
        b2 = -g_l2cy[k]; outIdx = GBB_OFF + p;
    }
    if (n == 0) { if (lane == 0) potOut[outIdx] = 0.f; return; }
    // pass 1: max (fma + fmax, no MUFU)
    float m2 = -3.4e38f;
    for (int c = lane; c < n; c += 32) {
        float t2 = (pot[c] - Crow[c]) * s1 + b2;
        m2 = fmaxf(m2, t2);
    }
#pragma unroll
    for (int o = 16; o; o >>= 1) m2 = fmaxf(m2, __shfl_xor_sync(0xffffffffu, m2, o));
    // pass 2: exp2 + sum (L1-hot reload)
    float S = 0.f;
    for (int c = lane; c < n; c += 32) {
        float t2 = (pot[c] - Crow[c]) * s1 + b2;
        S += ex2_fast(t2 - m2);
    }
#pragma unroll
    for (int o = 16; o; o >>= 1) S += __shfl_xor_sync(0xffffffffu, S, o);
    if (lane == 0) {
        float lse = (m2 + log2f(S)) * LN2_F;
        float outv = -eps * lse;
        potOut[outIdx] = finalMode ? outv : 0.5f * (potIn[outIdx] + outv);
    }
}

__global__ __launch_bounds__(1024, 1) void k_rounds(float* __restrict__ out) {
    __shared__ float seps[24], sinv[24];
    __shared__ int sns;
    __shared__ float sred[1024];
    int tid = threadIdx.x, lane = tid & 31, w = tid >> 5;
    int gwarp = blockIdx.x * 32 + w;
    int nwarps = gridDim.x * 32;
    if (tid == 0) {
        double e = 16.0; int c = 0;
        while (e > 0.0025) { seps[c] = (float)e; sinv[c] = (float)(1.0 / (double)(float)e); c++; e *= 0.64; }
        seps[c] = 0.0025f; sinv[c] = (float)(1.0 / (double)0.0025f); c++;
        sns = c;
    }
    __syncthreads();
    int ns = sns;
    for (int s = 0; s <= ns; s++) {
        int fin = (s == ns);
        int ei = fin ? ns - 1 : s;
        float eps = seps[ei];
        float s1 = sinv[ei] * LOG2E_F;
        const float* potIn = g_pot[s & 1];
        float* potOut = g_pot[(s + 1) & 1];
        for (int row = gwarp; row < 4 * 2048; row += nwarps)
            sink_row(row, potIn, potOut, eps, s1, fin, lane);
        grid_bar((unsigned)(s + 1) * gridDim.x);
    }
    // final reduction on block 0 only
    if (blockIdx.x == 0) {
        const float* pf = g_pot[(ns + 1) & 1];
        float acc = 0.f;
        for (int p = tid; p < NN; p += 1024) {
            int k = g_clx[p];
            if (g_valid[k]) acc += (pf[FAB_OFF + p] - pf[FAA_OFF + p]) / (float)g_cntx[k];
        }
        for (int p = tid; p < MM; p += 1024) {
            int k = g_cly[p];
            if (g_valid[k]) acc += (pf[GAB_OFF + p] - pf[GBB_OFF + p]) / (float)g_cnty[k];
        }
        sred[tid] = acc;
        __syncthreads();
        for (int s = 512; s; s >>= 1) {
            if (tid < s) sred[tid] += sred[tid + s];
            __syncthreads();
        }
        if (tid == 0) {
            out[0] = sred[0] + g_lossfil;
            g_barCnt = 0;   // reset for next graph replay (all blocks are past the last barrier)
        }
    }
}

// -------------------- host launch ------------------------------------------
extern "C" void kernel_launch(void* const* d_in, const int* in_sizes, int n_in,
                              void* d_out, int out_size) {
    const float* x    = (const float*)d_in[0];
    const float* cc   = (const float*)d_in[1];
    const float* fill = (const float*)d_in[2];
    const float* y    = (const float*)d_in[3];
    const int*   pred = (const int*)d_in[4];   // int32 or int64 (auto-detected on device)
    float* out = (float*)d_out;

    k_assign<<<(NN + 127) / 128, 128>>>(x, cc);
    k_norms<<<(NN + MM + 255) / 256, 256>>>(x, y);
    k_lists<<<1, 64>>>(pred, fill);
    k_cost<<<4 * (KC + NN / 64), 1024>>>(x, y);  // 160 blocks covers worst-case 64-row tiles
    k_rounds<<<GRIDB, 1024>>>(out);              // persistent: all 22 rounds + reduce
}

// round 4
// speedup vs baseline: 1.3330x; 1.2003x over previous
#include <cuda_runtime.h>
#include <math.h>

// Problem constants (fixed by the dataset)
#define NN 2048
#define MM 2048
#define KC 8
#define DD 64

// Compact potential layout: [fab(N) | gab(M) | faa(N) | gbb(M)]
#define FAB_OFF 0
#define GAB_OFF NN
#define FAA_OFF (NN + MM)
#define GBB_OFF (2 * NN + MM)
#define POT_SZ  (2 * (NN + MM))

#define LOG2E_F 1.4426950408889634f
#define LN2_F   0.6931471805599453f

#define GRIDB 148          // persistent kernel: one block per SM
#define COST_GRID 4416     // worst-case 64x64 tile count upper bound

// -------------------- static device scratch (no allocation allowed) ---------
__device__ int   g_predx[NN];
__device__ int   g_ix[NN], g_iy[MM];        // member indices grouped by cluster
__device__ int   g_clx[NN], g_cly[MM];      // cluster of compact position
__device__ int   g_cntx[KC], g_cnty[KC];
__device__ int   g_offx[KC + 1], g_offy[KC + 1];
__device__ int   g_offXY[KC + 1], g_offYX[KC + 1], g_offXX[KC + 1], g_offYY[KC + 1];
__device__ float g_l2cx[KC], g_l2cy[KC];    // log2(max(cnt,1))
__device__ int   g_valid[KC];
__device__ float g_lossfil;
__device__ int   g_tOff[4 * KC + 1];        // 2D 64x64 tile prefix for cost build
__device__ int   g_nT;
__device__ float g_hx[NN], g_hy[MM];        // 0.5*||p||^2
__device__ unsigned g_barCnt;               // grid barrier counter
__device__ unsigned g_exitCnt;              // exit counter (for safe reset)
// Compact cost matrices (worst case = one cluster owns everything)
__device__ float g_Cxy[(size_t)NN * MM];
__device__ float g_Cyx[(size_t)NN * MM];
__device__ float g_Cxx[(size_t)NN * NN];
__device__ float g_Cyy[(size_t)MM * MM];
__device__ float g_pot[2][POT_SZ];          // ping-pong potentials

__device__ __forceinline__ float ex2_fast(float x) {
    float r;
    asm("ex2.approx.ftz.f32 %0, %1;" : "=f"(r) : "f"(x));
    return r;
}

// -------------------- 1) kmeans assignment ---------------------------------
__global__ void k_assign(const float* __restrict__ x, const float* __restrict__ cc) {
    __shared__ float scc[KC * DD];
    for (int idx = threadIdx.x; idx < KC * DD; idx += blockDim.x) scc[idx] = cc[idx];
    __syncthreads();
    int i = blockIdx.x * blockDim.x + threadIdx.x;
    if (i >= NN) return;
    float xr[DD];
    const float4* xv = reinterpret_cast<const float4*>(x + (size_t)i * DD);
#pragma unroll
    for (int q = 0; q < DD / 4; q++) {
        float4 v = xv[q];
        xr[q * 4 + 0] = v.x; xr[q * 4 + 1] = v.y; xr[q * 4 + 2] = v.z; xr[q * 4 + 3] = v.w;
    }
    float best = 3.4e38f; int bk = 0;
#pragma unroll
    for (int k = 0; k < KC; k++) {
        float s = 0.f;
#pragma unroll 16
        for (int d = 0; d < DD; d++) {
            float t = xr[d] - scc[k * DD + d];
            s = fmaf(t, t, s);
        }
        if (s < best) { best = s; bk = k; }
    }
    g_predx[i] = bk;
}

// -------------------- 2) half squared norms --------------------------------
__global__ void k_norms(const float* __restrict__ x, const float* __restrict__ y) {
    int t = blockIdx.x * blockDim.x + threadIdx.x;
    if (t < NN) {
        const float4* v = reinterpret_cast<const float4*>(x + (size_t)t * DD);
        float s = 0.f;
#pragma unroll
        for (int q = 0; q < DD / 4; q++) { float4 a = v[q]; s += a.x*a.x + a.y*a.y + a.z*a.z + a.w*a.w; }
        g_hx[t] = 0.5f * s;
    } else if (t < NN + MM) {
        int j = t - NN;
        const float4* v = reinterpret_cast<const float4*>(y + (size_t)j * DD);
        float s = 0.f;
#pragma unroll
        for (int q = 0; q < DD / 4; q++) { float4 a = v[q]; s += a.x*a.x + a.y*a.y + a.z*a.z + a.w*a.w; }
        g_hy[j] = 0.5f * s;
    }
}

// -------------------- 3) deterministic member lists + offsets --------------
__global__ void k_lists(const int* __restrict__ predy32, const float* __restrict__ fill) {
    __shared__ int sBase[2][KC];
    __shared__ int sCnt[2][KC];
    __shared__ int sOr;
    int w = threadIdx.x >> 5, lane = threadIdx.x & 31;

    if (threadIdx.x == 0) sOr = 0;
    __syncthreads();
    int orv = 0;
    for (int i = threadIdx.x; i < MM / 2; i += blockDim.x) orv |= predy32[2 * i + 1];
    atomicOr(&sOr, orv);
    __syncthreads();
    const int stride = (sOr == 0) ? 2 : 1;   // int64 (odd words all 0) vs int32

    if (w < 2) {
        int nElem = (w == 0) ? NN : MM;
        int cnt[KC];
#pragma unroll
        for (int k = 0; k < KC; k++) cnt[k] = 0;
        for (int ch = 0; ch < nElem / 32; ch++) {
            int i = ch * 32 + lane;
            int v = (w == 0) ? g_predx[i] : (predy32[i * stride] & 7);
#pragma unroll
            for (int k = 0; k < KC; k++) cnt[k] += (v == k);
        }
#pragma unroll
        for (int k = 0; k < KC; k++) {
            int s = cnt[k];
            for (int o = 16; o; o >>= 1) s += __shfl_down_sync(0xffffffffu, s, o);
            if (lane == 0) sCnt[w][k] = s;
        }
        __syncwarp();
        if (lane == 0) {
            int off = 0;
            for (int k = 0; k < KC; k++) {
                int c = sCnt[w][k];
                sBase[w][k] = off;
                if (w == 0) { g_cntx[k] = c; g_offx[k] = off; }
                else        { g_cnty[k] = c; g_offy[k] = off; }
                off += c;
            }
            if (w == 0) g_offx[KC] = off; else g_offy[KC] = off;
        }
        __syncwarp();
        for (int ch = 0; ch < nElem / 32; ch++) {
            int i = ch * 32 + lane;
            int v = (w == 0) ? g_predx[i] : (predy32[i * stride] & 7);
            unsigned mask = __match_any_sync(0xffffffffu, v);
            unsigned lt = (1u << lane) - 1u;
            int rank = __popc(mask & lt);
            int myBase = sBase[w][v];
            __syncwarp();
            int pos = myBase + rank;
            if (w == 0) { g_ix[pos] = i; g_clx[pos] = v; }
            else        { g_iy[pos] = i; g_cly[pos] = v; }
            if ((mask & lt) == 0) sBase[w][v] = myBase + __popc(mask);
            __syncwarp();
        }
    }
    __syncthreads();
    if (threadIdx.x == 0) {
        float lf = 0.f;
        int oXY = 0, oYX = 0, oXX = 0, oYY = 0;
        for (int k = 0; k < KC; k++) {
            int cx = g_cntx[k], cy = g_cnty[k];
            float d = (float)cx / (float)NN - fill[k];
            lf += d * d;
            g_offXY[k] = oXY; g_offYX[k] = oYX; g_offXX[k] = oXX; g_offYY[k] = oYY;
            oXY += cx * cy; oYX += cy * cx; oXX += cx * cx; oYY += cy * cy;
            g_l2cx[k] = log2f((float)(cx > 0 ? cx : 1));
            g_l2cy[k] = log2f((float)(cy > 0 ? cy : 1));
            g_valid[k] = (cx > 0 && cy > 0) ? 1 : 0;
        }
        g_offXY[KC] = oXY; g_offYX[KC] = oYX; g_offXX[KC] = oXX; g_offYY[KC] = oYY;
        g_lossfil = lf / (float)KC;
        // 2D 64x64 tile prefix: families 0..3 have (rows, cols) = (cx,cy),(cy,cx),(cx,cx),(cy,cy)
        g_tOff[0] = 0;
        for (int f = 0; f < 4; f++)
            for (int k = 0; k < KC; k++) {
                int cx = g_cntx[k], cy = g_cnty[k];
                int nr = (f == 0 || f == 2) ? cx : cy;
                int nc = (f == 1 || f == 2) ? cx : cy;
                int idx = f * KC + k;
                g_tOff[idx + 1] = g_tOff[idx] + ((nr + 63) / 64) * ((nc + 63) / 64);
            }
        g_nT = g_tOff[4 * KC];
    }
    __syncthreads();
    for (int i = threadIdx.x; i < POT_SZ; i += blockDim.x) g_pot[0][i] = 0.f;
}

// -------------------- 4) compact cost submatrices (register-blocked) -------
// One block per 64x64 tile, 256 threads, 4x4 micro-tile per thread.
// Column tile stored d-major so each thread does 1x LDS.128 per d.
__global__ __launch_bounds__(256) void k_cost(const float* __restrict__ x,
                                              const float* __restrict__ y) {
    __shared__ float sR[64][65];        // [row][d], broadcast reads
    __shared__ float sCt[64][68];       // [d][col], float4 reads, 4-way store conflicts
    __shared__ float sHr[64], sHc[64];
    __shared__ int sOff[4 * KC + 1];
    int tid = threadIdx.x;
    if (tid < 4 * KC + 1) sOff[tid] = g_tOff[tid];
    __syncthreads();
    int bt = blockIdx.x;
    if (bt >= sOff[4 * KC]) return;
    int e = 0;
    while (bt >= sOff[e + 1]) e++;
    int f = e >> 3, k = e & 7;
    int ti = bt - sOff[e];
    int cx = g_cntx[k], cy = g_cnty[k], ox = g_offx[k], oy = g_offy[k];
    int nr, nc, obase;
    const int *rl, *cl; const float *rp, *cp, *rh, *chv; float* outp;
    if (f == 0)      { nr = cx; nc = cy; rl = g_ix + ox; cl = g_iy + oy; rp = x; cp = y; rh = g_hx; chv = g_hy; outp = g_Cxy; obase = g_offXY[k]; }
    else if (f == 1) { nr = cy; nc = cx; rl = g_iy + oy; cl = g_ix + ox; rp = y; cp = x; rh = g_hy; chv = g_hx; outp = g_Cyx; obase = g_offYX[k]; }
    else if (f == 2) { nr = cx; nc = cx; rl = g_ix + ox; cl = g_ix + ox; rp = x; cp = x; rh = g_hx; chv = g_hx; outp = g_Cxx; obase = g_offXX[k]; }
    else             { nr = cy; nc = cy; rl = g_iy + oy; cl = g_iy + oy; rp = y; cp = y; rh = g_hy; chv = g_hy; outp = g_Cyy; obase = g_offYY[k]; }
    int nct = (nc + 63) >> 6;
    int r0 = (ti / nct) * 64;
    int c0 = (ti % nct) * 64;

    // fills: coalesced gmem reads (d fastest)
    for (int idx = tid; idx < 64 * DD; idx += 256) {
        int r = idx >> 6, d = idx & 63;
        int gi = rl[min(r0 + r, nr - 1)];
        sR[r][d] = rp[(size_t)gi * DD + d];
    }
    for (int idx = tid; idx < 64 * DD; idx += 256) {
        int c = idx >> 6, d = idx & 63;
        int gi = cl[min(c0 + c, nc - 1)];
        sCt[d][c] = cp[(size_t)gi * DD + d];
    }
    if (tid < 64)       sHr[tid]      = rh[rl[min(r0 + tid, nr - 1)]];
    else if (tid < 128) sHc[tid - 64] = chv[cl[min(c0 + tid - 64, nc - 1)]];
    __syncthreads();

    int rg = tid >> 4;       // 0..15 -> rows rg*4 .. rg*4+3
    int cg = tid & 15;       // 0..15 -> cols cg*4 .. cg*4+3
    float acc[4][4];
#pragma unroll
    for (int i = 0; i < 4; i++)
#pragma unroll
        for (int j = 0; j < 4; j++) acc[i][j] = 0.f;

#pragma unroll 8
    for (int d = 0; d < DD; d++) {
        float4 cv = *reinterpret_cast<const float4*>(&sCt[d][cg * 4]);
        float r0v = sR[rg * 4 + 0][d];
        float r1v = sR[rg * 4 + 1][d];
        float r2v = sR[rg * 4 + 2][d];
        float r3v = sR[rg * 4 + 3][d];
        acc[0][0] = fmaf(r0v, cv.x, acc[0][0]); acc[0][1] = fmaf(r0v, cv.y, acc[0][1]);
        acc[0][2] = fmaf(r0v, cv.z, acc[0][2]); acc[0][3] = fmaf(r0v, cv.w, acc[0][3]);
        acc[1][0] = fmaf(r1v, cv.x, acc[1][0]); acc[1][1] = fmaf(r1v, cv.y, acc[1][1]);
        acc[1][2] = fmaf(r1v, cv.z, acc[1][2]); acc[1][3] = fmaf(r1v, cv.w, acc[1][3]);
        acc[2][0] = fmaf(r2v, cv.x, acc[2][0]); acc[2][1] = fmaf(r2v, cv.y, acc[2][1]);
        acc[2][2] = fmaf(r2v, cv.z, acc[2][2]); acc[2][3] = fmaf(r2v, cv.w, acc[2][3]);
        acc[3][0] = fmaf(r3v, cv.x, acc[3][0]); acc[3][1] = fmaf(r3v, cv.y, acc[3][1]);
        acc[3][2] = fmaf(r3v, cv.z, acc[3][2]); acc[3][3] = fmaf(r3v, cv.w, acc[3][3]);
    }

#pragma unroll
    for (int i = 0; i < 4; i++) {
        int rr = r0 + rg * 4 + i;
        if (rr < nr) {
            float hr = sHr[rg * 4 + i];
            size_t rowb = (size_t)obase + (size_t)rr * nc;
#pragma unroll
            for (int j = 0; j < 4; j++) {
                int cc = c0 + cg * 4 + j;
                if (cc < nc) outp[rowb + cc] = fmaxf(hr + sHc[cg * 4 + j] - acc[i][j], 0.f);
            }
        }
    }
}

// -------------------- 5) persistent fused Sinkhorn rounds ------------------
__device__ __forceinline__ void grid_bar(unsigned target) {
    __syncthreads();
    if (threadIdx.x == 0) {
        __threadfence();
        atomicAdd(&g_barCnt, 1u);
        while (*((volatile unsigned*)&g_barCnt) < target) { }
        __threadfence();
    }
    __syncthreads();
}

__device__ __forceinline__ void sink_row(int row, const float* __restrict__ potIn,
                                         float* __restrict__ potOut,
                                         float eps, float s1, int finalMode, int lane) {
    int fam = row >> 11;
    int p = row & 2047;
    int k, n, outIdx;
    const float *Crow, *pot;
    float b2;
    if (fam == 0) {
        k = g_clx[p]; n = g_cnty[k];
        Crow = g_Cxy + (size_t)g_offXY[k] + (size_t)(p - g_offx[k]) * n;
        pot = potIn + GAB_OFF + g_offy[k];
        b2 = -g_l2cy[k]; outIdx = FAB_OFF + p;
    } else if (fam == 1) {
        k = g_cly[p]; n = g_cntx[k];
        Crow = g_Cyx + (size_t)g_offYX[k] + (size_t)(p - g_offy[k]) * n;
        pot = potIn + FAB_OFF + g_offx[k];
        b2 = -g_l2cx[k]; outIdx = GAB_OFF + p;
    } else if (fam == 2) {
        k = g_clx[p]; n = g_cntx[k];
        Crow = g_Cxx + (size_t)g_offXX[k] + (size_t)(p - g_offx[k]) * n;
        pot = potIn + FAA_OFF + g_offx[k];
        b2 = -g_l2cx[k]; outIdx = FAA_OFF + p;
    } else {
        k = g_cly[p]; n = g_cnty[k];
        Crow = g_Cyy + (size_t)g_offYY[k] + (size_t)(p - g_offy[k]) * n;
        pot = potIn + GBB_OFF + g_offy[k];
        b2 = -g_l2cy[k]; outIdx = GBB_OFF + p;
    }
    if (n == 0) { if (lane == 0) potOut[outIdx] = 0.f; return; }
    float m2 = -3.4e38f, S = 0.f;
    if (n <= 512) {
        // fast path: cache (pot-C)/eps in regs, MLP=16, no reloads in pass 2
        float tv[16];
#pragma unroll
        for (int q = 0; q < 16; q++) {
            float v = -3.4e38f;
            if (q * 32 < n) {               // warp-uniform guard
                int c = min(q * 32 + lane, n - 1);
                v = fmaf(pot[c] - Crow[c], s1, b2);
                if (q * 32 + lane >= n) v = -3.4e38f;
            }
            tv[q] = v;
        }
#pragma unroll
        for (int q = 0; q < 16; q++) m2 = fmaxf(m2, tv[q]);
#pragma unroll
        for (int o = 16; o; o >>= 1) m2 = fmaxf(m2, __shfl_xor_sync(0xffffffffu, m2, o));
#pragma unroll
        for (int q = 0; q < 16; q++) S += ex2_fast(tv[q] - m2);   // masked -> exp2(-huge)=0
    } else {
        for (int c = lane; c < n; c += 32)
            m2 = fmaxf(m2, fmaf(pot[c] - Crow[c], s1, b2));
#pragma unroll
        for (int o = 16; o; o >>= 1) m2 = fmaxf(m2, __shfl_xor_sync(0xffffffffu, m2, o));
        for (int c = lane; c < n; c += 32)
            S += ex2_fast(fmaf(pot[c] - Crow[c], s1, b2) - m2);
    }
#pragma unroll
    for (int o = 16; o; o >>= 1) S += __shfl_xor_sync(0xffffffffu, S, o);
    if (lane == 0) {
        float lse = (m2 + log2f(S)) * LN2_F;
        float outv = -eps * lse;
        potOut[outIdx] = finalMode ? outv : 0.5f * (potIn[outIdx] + outv);
    }
}

__global__ __launch_bounds__(1024, 1) void k_rounds(float* __restrict__ out) {
    __shared__ float seps[24], sinv[24];
    __shared__ int sns;
    __shared__ float sred[1024];
    int tid = threadIdx.x, lane = tid & 31, w = tid >> 5;
    int gwarp = blockIdx.x * 32 + w;
    int nwarps = gridDim.x * 32;
    if (tid == 0) {
        double e = 16.0; int c = 0;
        while (e > 0.0025) { seps[c] = (float)e; sinv[c] = (float)(1.0 / (double)(float)e); c++; e *= 0.64; }
        seps[c] = 0.0025f; sinv[c] = (float)(1.0 / (double)0.0025f); c++;
        sns = c;
    }
    __syncthreads();
    int ns = sns;
    for (int s = 0; s <= ns; s++) {
        int fin = (s == ns);
        int ei = fin ? ns - 1 : s;
        float eps = seps[ei];
        float s1 = sinv[ei] * LOG2E_F;
        const float* potIn = g_pot[s & 1];
        float* potOut = g_pot[(s + 1) & 1];
        for (int row = gwarp; row < 4 * 2048; row += nwarps)
            sink_row(row, potIn, potOut, eps, s1, fin, lane);
        grid_bar((unsigned)(s + 1) * gridDim.x);
    }
    // non-zero blocks: signal exit and leave
    if (blockIdx.x != 0) {
        if (tid == 0) atomicAdd(&g_exitCnt, 1u);
        return;
    }
    // block 0: final reduction
    const float* pf = g_pot[(ns + 1) & 1];
    float acc = 0.f;
    for (int p = tid; p < NN; p += 1024) {
        int k = g_clx[p];
        if (g_valid[k]) acc += (pf[FAB_OFF + p] - pf[FAA_OFF + p]) / (float)g_cntx[k];
    }
    for (int p = tid; p < MM; p += 1024) {
        int k = g_cly[p];
        if (g_valid[k]) acc += (pf[GAB_OFF + p] - pf[GBB_OFF + p]) / (float)g_cnty[k];
    }
    sred[tid] = acc;
    __syncthreads();
    for (int s = 512; s; s >>= 1) {
        if (tid < s) sred[tid] += sred[tid + s];
        __syncthreads();
    }
    if (tid == 0) {
        out[0] = sred[0] + g_lossfil;
        // safe counter reset: wait until every other block is past its last poll
        while (*((volatile unsigned*)&g_exitCnt) < (unsigned)(gridDim.x - 1)) { }
        g_barCnt = 0;
        g_exitCnt = 0;
    }
}

// -------------------- host launch ------------------------------------------
extern "C" void kernel_launch(void* const* d_in, const int* in_sizes, int n_in,
                              void* d_out, int out_size) {
    const float* x    = (const float*)d_in[0];
    const float* cc   = (const float*)d_in[1];
    const float* fill = (const float*)d_in[2];
    const float* y    = (const float*)d_in[3];
    const int*   pred = (const int*)d_in[4];   // int32 or int64 (auto-detected on device)
    float* out = (float*)d_out;

    k_assign<<<(NN + 127) / 128, 128>>>(x, cc);
    k_norms<<<(NN + MM + 255) / 256, 256>>>(x, y);
    k_lists<<<1, 64>>>(pred, fill);
    k_cost<<<COST_GRID, 256>>>(x, y);           // one 64x64 tile per block, excess blocks exit
    k_rounds<<<GRIDB, 1024>>>(out);             // persistent: all 22 rounds + reduce
}

// round 6
// speedup vs baseline: 1.4651x; 1.0992x over previous
#include <cuda_runtime.h>
#include <math.h>

#define NN 2048
#define MM 2048
#define KC 8
#define DD 64

#define FAB_OFF 0
#define GAB_OFF NN
#define FAA_OFF (NN + MM)
#define GBB_OFF (2 * NN + MM)
#define POT_SZ  (2 * (NN + MM))
#define NROWS   (4 * 2048)

#define LOG2E_F 1.4426950408889634f
#define LN2_F   0.6931471805599453f
#define SENT    -3.4e38f

#define GRIDB 148
#define COST_GRID 4416

// -------------------- static device scratch ---------------------------------
__device__ int   g_predx[NN];
__device__ int   g_ix[NN], g_iy[MM];
__device__ int   g_clx[NN], g_cly[MM];
__device__ int   g_cntx[KC], g_cnty[KC];
__device__ int   g_offx[KC + 1], g_offy[KC + 1];
__device__ int   g_offXY[KC + 1], g_offYX[KC + 1], g_offXX[KC + 1], g_offYY[KC + 1];
__device__ float g_l2cx[KC], g_l2cy[KC];
__device__ int   g_valid[KC];
__device__ float g_lossfil;
__device__ int   g_tOff[4 * KC + 1];
__device__ float g_hx[NN], g_hy[MM];
__device__ unsigned g_barCnt;
__device__ unsigned g_exitCnt;
// row descriptors (computed once, read every round)
__device__ const float* g_rowC[NROWS];
__device__ int   g_rowPot[NROWS];
__device__ int   g_rowN[NROWS];
__device__ float g_rowB2[NROWS];
// cost matrices
__device__ float g_Cxy[(size_t)NN * MM];
__device__ float g_Cyx[(size_t)NN * MM];
__device__ float g_Cxx[(size_t)NN * NN];
__device__ float g_Cyy[(size_t)MM * MM];
__device__ float g_pot[2][POT_SZ];

__device__ __forceinline__ float ex2_fast(float x) {
    float r;
    asm("ex2.approx.ftz.f32 %0, %1;" : "=f"(r) : "f"(x));
    return r;
}

// -------------------- 1) fused assign + norms -------------------------------
__global__ void k_prep(const float* __restrict__ x, const float* __restrict__ cc,
                       const float* __restrict__ y) {
    __shared__ float scc[KC * DD];
    for (int idx = threadIdx.x; idx < KC * DD; idx += blockDim.x) scc[idx] = cc[idx];
    __syncthreads();
    int t = blockIdx.x * blockDim.x + threadIdx.x;
    if (t < NN) {
        float xr[DD];
        float nrm = 0.f;
        const float4* xv = reinterpret_cast<const float4*>(x + (size_t)t * DD);
#pragma unroll
        for (int q = 0; q < DD / 4; q++) {
            float4 v = xv[q];
            xr[q*4+0]=v.x; xr[q*4+1]=v.y; xr[q*4+2]=v.z; xr[q*4+3]=v.w;
            nrm += v.x*v.x + v.y*v.y + v.z*v.z + v.w*v.w;
        }
        g_hx[t] = 0.5f * nrm;
        float best = 3.4e38f; int bk = 0;
#pragma unroll
        for (int k = 0; k < KC; k++) {
            float s = 0.f;
#pragma unroll 16
            for (int d = 0; d < DD; d++) {
                float u = xr[d] - scc[k * DD + d];
                s = fmaf(u, u, s);
            }
            if (s < best) { best = s; bk = k; }
        }
        g_predx[t] = bk;
    } else if (t < NN + MM) {
        int j = t - NN;
        const float4* v = reinterpret_cast<const float4*>(y + (size_t)j * DD);
        float s = 0.f;
#pragma unroll
        for (int q = 0; q < DD / 4; q++) { float4 a = v[q]; s += a.x*a.x + a.y*a.y + a.z*a.z + a.w*a.w; }
        g_hy[j] = 0.5f * s;
    }
}

// -------------------- 2) lists + offsets + row descriptors ------------------
__global__ void k_lists(const int* __restrict__ predy32, const float* __restrict__ fill) {
    __shared__ int sBase[2][KC];
    __shared__ int sCnt[2][KC];
    __shared__ int sOr;
    int w = threadIdx.x >> 5, lane = threadIdx.x & 31;

    if (threadIdx.x == 0) sOr = 0;
    __syncthreads();
    int orv = 0;
    for (int i = threadIdx.x; i < MM / 2; i += blockDim.x) orv |= predy32[2 * i + 1];
    atomicOr(&sOr, orv);
    __syncthreads();
    const int stride = (sOr == 0) ? 2 : 1;   // int64 (odd words 0) vs int32

    if (w < 2) {
        int nElem = (w == 0) ? NN : MM;
        int cnt[KC];
#pragma unroll
        for (int k = 0; k < KC; k++) cnt[k] = 0;
        for (int ch = 0; ch < nElem / 32; ch++) {
            int i = ch * 32 + lane;
            int v = (w == 0) ? g_predx[i] : (predy32[i * stride] & 7);
#pragma unroll
            for (int k = 0; k < KC; k++) cnt[k] += (v == k);
        }
#pragma unroll
        for (int k = 0; k < KC; k++) {
            int s = cnt[k];
            for (int o = 16; o; o >>= 1) s += __shfl_down_sync(0xffffffffu, s, o);
            if (lane == 0) sCnt[w][k] = s;
        }
        __syncwarp();
        if (lane == 0) {
            int off = 0;
            for (int k = 0; k < KC; k++) {
                int c = sCnt[w][k];
                sBase[w][k] = off;
                if (w == 0) { g_cntx[k] = c; g_offx[k] = off; }
                else        { g_cnty[k] = c; g_offy[k] = off; }
                off += c;
            }
            if (w == 0) g_offx[KC] = off; else g_offy[KC] = off;
        }
        __syncwarp();
        for (int ch = 0; ch < nElem / 32; ch++) {
            int i = ch * 32 + lane;
            int v = (w == 0) ? g_predx[i] : (predy32[i * stride] & 7);
            unsigned mask = __match_any_sync(0xffffffffu, v);
            unsigned lt = (1u << lane) - 1u;
            int rank = __popc(mask & lt);
            int myBase = sBase[w][v];
            __syncwarp();
            int pos = myBase + rank;
            if (w == 0) { g_ix[pos] = i; g_clx[pos] = v; }
            else        { g_iy[pos] = i; g_cly[pos] = v; }
            if ((mask & lt) == 0) sBase[w][v] = myBase + __popc(mask);
            __syncwarp();
        }
    }
    __syncthreads();
    if (threadIdx.x == 0) {
        float lf = 0.f;
        int oXY = 0, oYX = 0, oXX = 0, oYY = 0;
        for (int k = 0; k < KC; k++) {
            int cx = g_cntx[k], cy = g_cnty[k];
            float d = (float)cx / (float)NN - fill[k];
            lf += d * d;
            g_offXY[k] = oXY; g_offYX[k] = oYX; g_offXX[k] = oXX; g_offYY[k] = oYY;
            oXY += cx * cy; oYX += cy * cx; oXX += cx * cx; oYY += cy * cy;
            g_l2cx[k] = log2f((float)(cx > 0 ? cx : 1));
            g_l2cy[k] = log2f((float)(cy > 0 ? cy : 1));
            g_valid[k] = (cx > 0 && cy > 0) ? 1 : 0;
        }
        g_offXY[KC] = oXY; g_offYX[KC] = oYX; g_offXX[KC] = oXX; g_offYY[KC] = oYY;
        g_lossfil = lf / (float)KC;
        g_tOff[0] = 0;
        for (int f = 0; f < 4; f++)
            for (int k = 0; k < KC; k++) {
                int cx = g_cntx[k], cy = g_cnty[k];
                int nr = (f == 0 || f == 2) ? cx : cy;
                int nc = (f == 1 || f == 2) ? cx : cy;
                int idx = f * KC + k;
                g_tOff[idx + 1] = g_tOff[idx] + ((nr + 63) / 64) * ((nc + 63) / 64);
            }
    }
    __syncthreads();
    // row descriptors + potential init
    for (int row = threadIdx.x; row < NROWS; row += blockDim.x) {
        int fam = row >> 11, p = row & 2047;
        int k, n, potOff; const float* C; float b2;
        if (fam == 0) {
            k = g_clx[p]; n = g_cnty[k];
            C = g_Cxy + (size_t)g_offXY[k] + (size_t)(p - g_offx[k]) * n;
            potOff = GAB_OFF + g_offy[k]; b2 = -g_l2cy[k];
        } else if (fam == 1) {
            k = g_cly[p]; n = g_cntx[k];
            C = g_Cyx + (size_t)g_offYX[k] + (size_t)(p - g_offy[k]) * n;
            potOff = FAB_OFF + g_offx[k]; b2 = -g_l2cx[k];
        } else if (fam == 2) {
            k = g_clx[p]; n = g_cntx[k];
            C = g_Cxx + (size_t)g_offXX[k] + (size_t)(p - g_offx[k]) * n;
            potOff = FAA_OFF + g_offx[k]; b2 = -g_l2cx[k];
        } else {
            k = g_cly[p]; n = g_cnty[k];
            C = g_Cyy + (size_t)g_offYY[k] + (size_t)(p - g_offy[k]) * n;
            potOff = GBB_OFF + g_offy[k]; b2 = -g_l2cy[k];
        }
        g_rowC[row] = C; g_rowPot[row] = potOff; g_rowN[row] = n; g_rowB2[row] = b2;
    }
    for (int i = threadIdx.x; i < POT_SZ; i += blockDim.x) g_pot[0][i] = 0.f;
}

// -------------------- 3) compact cost submatrices ---------------------------
__global__ __launch_bounds__(256) void k_cost(const float* __restrict__ x,
                                              const float* __restrict__ y) {
    __shared__ float sR[64][65];
    __shared__ float sCt[64][68];
    __shared__ float sHr[64], sHc[64];
    __shared__ int sOff[4 * KC + 1];
    int tid = threadIdx.x;
    if (tid < 4 * KC + 1) sOff[tid] = g_tOff[tid];
    __syncthreads();
    int bt = blockIdx.x;
    if (bt >= sOff[4 * KC]) return;
    int e = 0;
    while (bt >= sOff[e + 1]) e++;
    int f = e >> 3, k = e & 7;
    int ti = bt - sOff[e];
    int cx = g_cntx[k], cy = g_cnty[k], ox = g_offx[k], oy = g_offy[k];
    int nr, nc, obase;
    const int *rl, *cl; const float *rp, *cp, *rh, *chv; float* outp;
    if (f == 0)      { nr = cx; nc = cy; rl = g_ix + ox; cl = g_iy + oy; rp = x; cp = y; rh = g_hx; chv = g_hy; outp = g_Cxy; obase = g_offXY[k]; }
    else if (f == 1) { nr = cy; nc = cx; rl = g_iy + oy; cl = g_ix + ox; rp = y; cp = x; rh = g_hy; chv = g_hx; outp = g_Cyx; obase = g_offYX[k]; }
    else if (f == 2) { nr = cx; nc = cx; rl = g_ix + ox; cl = g_ix + ox; rp = x; cp = x; rh = g_hx; chv = g_hx; outp = g_Cxx; obase = g_offXX[k]; }
    else             { nr = cy; nc = cy; rl = g_iy + oy; cl = g_iy + oy; rp = y; cp = y; rh = g_hy; chv = g_hy; outp = g_Cyy; obase = g_offYY[k]; }
    int nct = (nc + 63) >> 6;
    int r0 = (ti / nct) * 64;
    int c0 = (ti % nct) * 64;

    for (int idx = tid; idx < 64 * DD; idx += 256) {
        int r = idx >> 6, d = idx & 63;
        int gi = rl[min(r0 + r, nr - 1)];
        sR[r][d] = rp[(size_t)gi * DD + d];
    }
    for (int idx = tid; idx < 64 * DD; idx += 256) {
        int c = idx >> 6, d = idx & 63;
        int gi = cl[min(c0 + c, nc - 1)];
        sCt[d][c] = cp[(size_t)gi * DD + d];
    }
    if (tid < 64)       sHr[tid]      = rh[rl[min(r0 + tid, nr - 1)]];
    else if (tid < 128) sHc[tid - 64] = chv[cl[min(c0 + tid - 64, nc - 1)]];
    __syncthreads();

    int rg = tid >> 4, cg = tid & 15;
    float acc[4][4];
#pragma unroll
    for (int i = 0; i < 4; i++)
#pragma unroll
        for (int j = 0; j < 4; j++) acc[i][j] = 0.f;

#pragma unroll 8
    for (int d = 0; d < DD; d++) {
        float4 cv = *reinterpret_cast<const float4*>(&sCt[d][cg * 4]);
        float r0v = sR[rg * 4 + 0][d];
        float r1v = sR[rg * 4 + 1][d];
        float r2v = sR[rg * 4 + 2][d];
        float r3v = sR[rg * 4 + 3][d];
        acc[0][0]=fmaf(r0v,cv.x,acc[0][0]); acc[0][1]=fmaf(r0v,cv.y,acc[0][1]);
        acc[0][2]=fmaf(r0v,cv.z,acc[0][2]); acc[0][3]=fmaf(r0v,cv.w,acc[0][3]);
        acc[1][0]=fmaf(r1v,cv.x,acc[1][0]); acc[1][1]=fmaf(r1v,cv.y,acc[1][1]);
        acc[1][2]=fmaf(r1v,cv.z,acc[1][2]); acc[1][3]=fmaf(r1v,cv.w,acc[1][3]);
        acc[2][0]=fmaf(r2v,cv.x,acc[2][0]); acc[2][1]=fmaf(r2v,cv.y,acc[2][1]);
        acc[2][2]=fmaf(r2v,cv.z,acc[2][2]); acc[2][3]=fmaf(r2v,cv.w,acc[2][3]);
        acc[3][0]=fmaf(r3v,cv.x,acc[3][0]); acc[3][1]=fmaf(r3v,cv.y,acc[3][1]);
        acc[3][2]=fmaf(r3v,cv.z,acc[3][2]); acc[3][3]=fmaf(r3v,cv.w,acc[3][3]);
    }

#pragma unroll
    for (int i = 0; i < 4; i++) {
        int rr = r0 + rg * 4 + i;
        if (rr < nr) {
            float hr = sHr[rg * 4 + i];
            size_t rowb = (size_t)obase + (size_t)rr * nc;
#pragma unroll
            for (int j = 0; j < 4; j++) {
                int cc = c0 + cg * 4 + j;
                if (cc < nc) outp[rowb + cc] = fmaxf(hr + sHc[cg * 4 + j] - acc[i][j], 0.f);
            }
        }
    }
}

// -------------------- 4) persistent fused Sinkhorn rounds -------------------
__device__ __forceinline__ void grid_bar(unsigned target) {
    __syncthreads();
    if (threadIdx.x == 0) {
        __threadfence();
        atomicAdd(&g_barCnt, 1u);
        while (*((volatile unsigned*)&g_barCnt) < target) { __nanosleep(32); }
        __threadfence();
    }
    __syncthreads();
}

// one-pass online logsumexp over a row of any length; 256-col register tiles.
__device__ __forceinline__ void sink_row(int row, const float* __restrict__ potIn,
                                         float* __restrict__ potOut,
                                         float eps, float s1, int finalMode, int lane) {
    int n = g_rowN[row];
    if (n == 0) {
        if (lane == 0) potOut[row] = 0.f;
        return;
    }
    const float* __restrict__ Crow = g_rowC[row];
    const float* __restrict__ pot = potIn + g_rowPot[row];
    float b2 = g_rowB2[row];

    float m = SENT, S = 0.f;
    for (int base = 0; base < n; base += 256) {
        int lim = n - base;                      // >= 1
        float tv[8];
#pragma unroll
        for (int q = 0; q < 8; q++) {
            float v = SENT;
            if (q * 32 < lim) {                  // warp-uniform
                int idx = q * 32 + lane;
                int c = base + min(idx, lim - 1);
                v = fmaf(pot[c] - Crow[c], s1, b2);
                if (idx >= lim) v = SENT;
            }
            tv[q] = v;
        }
        float mt = tv[0];
#pragma unroll
        for (int q = 1; q < 8; q++) mt = fmaxf(mt, tv[q]);
        float c2 = fmaxf(m, mt);
        float Sn = S * ex2_fast(m - c2);         // both-SENT -> ex2(0)*0 = 0, fine
#pragma unroll
        for (int q = 0; q < 8; q++) Sn += ex2_fast(tv[q] - c2);  // masked lanes: ex2(SENT-c2)=0
        m = c2; S = Sn;
    }
    // cross-lane (m,S) merge; SENT lanes contribute S*ex2(SENT-real)=0
#pragma unroll
    for (int o = 16; o; o >>= 1) {
        float mo = __shfl_xor_sync(0xffffffffu, m, o);
        float So = __shfl_xor_sync(0xffffffffu, S, o);
        float c2 = fmaxf(m, mo);
        S = S * ex2_fast(m - c2) + So * ex2_fast(mo - c2);
        m = c2;
    }
    if (lane == 0) {
        float lse = (m + log2f(S)) * LN2_F;
        float outv = -eps * lse;
        potOut[row] = finalMode ? outv : 0.5f * (potIn[row] + outv);
    }
}

__global__ __launch_bounds__(1024, 1) void k_rounds(float* __restrict__ out) {
    __shared__ float seps[24], sinv[24];
    __shared__ int sns;
    __shared__ float sred[1024];
    int tid = threadIdx.x, lane = tid & 31, w = tid >> 5;
    int gwarp = blockIdx.x * 32 + w;
    int nwarps = gridDim.x * 32;
    if (tid == 0) {
        double e = 16.0; int c = 0;
        while (e > 0.0025) { seps[c] = (float)e; sinv[c] = (float)(1.0 / (double)(float)e); c++; e *= 0.64; }
        seps[c] = 0.0025f; sinv[c] = (float)(1.0 / (double)0.0025f); c++;
        sns = c;
    }
    __syncthreads();
    int ns = sns;
    for (int s = 0; s <= ns; s++) {
        int fin = (s == ns);
        int ei = fin ? ns - 1 : s;
        float eps = seps[ei];
        float s1 = sinv[ei] * LOG2E_F;
        const float* potIn = g_pot[s & 1];
        float* potOut = g_pot[(s + 1) & 1];
        for (int row = gwarp; row < NROWS; row += nwarps)
            sink_row(row, potIn, potOut, eps, s1, fin, lane);
        grid_bar((unsigned)(s + 1) * gridDim.x);
    }
    if (blockIdx.x != 0) {
        if (tid == 0) atomicAdd(&g_exitCnt, 1u);
        return;
    }
    const float* pf = g_pot[(ns + 1) & 1];
    float acc = 0.f;
    for (int p = tid; p < NN; p += 1024) {
        int k = g_clx[p];
        if (g_valid[k]) acc += (pf[FAB_OFF + p] - pf[FAA_OFF + p]) / (float)g_cntx[k];
    }
    for (int p = tid; p < MM; p += 1024) {
        int k = g_cly[p];
        if (g_valid[k]) acc += (pf[GAB_OFF + p] - pf[GBB_OFF + p]) / (float)g_cnty[k];
    }
    sred[tid] = acc;
    __syncthreads();
    for (int s = 512; s; s >>= 1) {
        if (tid < s) sred[tid] += sred[tid + s];
        __syncthreads();
    }
    if (tid == 0) {
        out[0] = sred[0] + g_lossfil;
        while (*((volatile unsigned*)&g_exitCnt) < (unsigned)(gridDim.x - 1)) { __nanosleep(32); }
        g_barCnt = 0;
        g_exitCnt = 0;
    }
}

// -------------------- host launch -------------------------------------------
extern "C" void kernel_launch(void* const* d_in, const int* in_sizes, int n_in,
                              void* d_out, int out_size) {
    const float* x    = (const float*)d_in[0];
    const float* cc   = (const float*)d_in[1];
    const float* fill = (const float*)d_in[2];
    const float* y    = (const float*)d_in[3];
    const int*   pred = (const int*)d_in[4];
    float* out = (float*)d_out;

    k_prep<<<(NN + MM + 255) / 256, 256>>>(x, cc, y);
    k_lists<<<1, 256>>>(pred, fill);
    k_cost<<<COST_GRID, 256>>>(x, y);
    k_rounds<<<GRIDB, 1024>>>(out);
}